// round 1
// baseline (speedup 1.0000x reference)
#include <cuda_runtime.h>

#define CC 128
#define AA 64
#define KN 24
#define SS 4
#define NP 276        // 24*23/2
#define NPAIR 10
#define AEVDIM 384
#define RAD 64

// AEV scratch (12.6 MB) — __device__ global per allocation rules
__device__ float g_aev[CC * AA * AEVDIM];

__constant__ int c_triu[16] = {0,1,2,3, 1,4,5,6, 2,5,7,8, 3,6,8,9};
// cos/sin of shfz = (k+0.5)*pi/8
__constant__ float c_cz[8] = { 0.98078528f, 0.83146961f, 0.55557023f, 0.19509032f,
                              -0.19509032f,-0.55557023f,-0.83146961f,-0.98078528f};
__constant__ float c_sz[8] = { 0.19509032f, 0.55557023f, 0.83146961f, 0.98078528f,
                               0.98078528f, 0.83146961f, 0.55557023f, 0.19509032f};

// ---------------------------------------------------------------------------
// Kernel 1: AEV per atom. One block (128 threads) per atom.
// ---------------------------------------------------------------------------
__global__ __launch_bounds__(128) void aev_kernel(
    const int* __restrict__ elem, const int* __restrict__ nbr,
    const float* __restrict__ dist, const float* __restrict__ diff)
{
    const int id  = blockIdx.x;      // c*64 + a
    const int c   = id >> 6;
    const int tid = threadIdx.x;

    __shared__ float sd[KN], sfca[KN];
    __shared__ float su[KN][3];
    __shared__ int   sspec[KN];
    __shared__ float aev[AEVDIM];
    __shared__ float pq[NP], psn[NP], pfc[NP];
    __shared__ float pf2[4][NP];
    __shared__ int   ppi[NP];
    __shared__ float ascr[4][NPAIR][32];

    float my_fcr = 0.f;
    if (tid < KN) {
        float d = dist[id * KN + tid];
        sd[tid] = d;
        const float PI = 3.14159265358979f;
        my_fcr     = (d < 5.2f) ? (0.5f * __cosf(PI * d / 5.2f) + 0.5f) : 0.f;
        sfca[tid]  = (d < 3.5f) ? (0.5f * __cosf(PI * d / 3.5f) + 0.5f) : 0.f;
        float inv = 1.0f / d;
        su[tid][0] = diff[(id * KN + tid) * 3 + 0] * inv;
        su[tid][1] = diff[(id * KN + tid) * 3 + 1] * inv;
        su[tid][2] = diff[(id * KN + tid) * 3 + 2] * inv;
        sspec[tid] = elem[c * AA + nbr[id * KN + tid]];
    }
    for (int t = tid; t < AEVDIM; t += 128) aev[t] = 0.f;
    __syncthreads();

    // ---- radial: chain of exp factors starting at nearest shift ----
    // shfr_i = 0.9 + 0.26875*i ; eta_R = 16
    if (tid < KN) {
        float d     = sd[tid];
        int   sp    = sspec[tid];
        float scale = 0.25f * my_fcr;
        float t     = d - 0.9f;
        int istar = __float2int_rn(t * 3.7209302f);   // 1/0.26875
        istar = max(0, min(15, istar));
        float ds  = t - 0.26875f * (float)istar;
        float epk = __expf(-16.f * ds * ds);
        const float WW = 0.09913725f;                  // exp(-2*1.155625)
        // upward
        float e = epk;
        float w = __expf(8.6f * t - 1.155625f * (2.f * istar + 1.f));
        for (int r = istar; r < 16; r++) {
            atomicAdd(&aev[sp * 16 + r], scale * e);
            e *= w; w *= WW;
        }
        // downward
        e = epk;
        w = __expf(-8.6f * t + 1.155625f * (2.f * istar - 1.f));
        for (int r = istar - 1; r >= 0; r--) {
            e *= w; w *= WW;
            atomicAdd(&aev[sp * 16 + r], scale * e);
        }
    }

    // ---- angular stage 1: per-pair quantities ----
    for (int p = tid; p < NP; p += 128) {
        int j = 0, rem = p;
        while (rem >= KN - 1 - j) { rem -= KN - 1 - j; j++; }
        int k2 = j + 1 + rem;

        float d1 = sd[j], d2 = sd[k2];
        float dot = su[j][0]*su[k2][0] + su[j][1]*su[k2][1] + su[j][2]*su[k2][2];
        float q = 0.95f * dot;
        pq[p]  = q;
        psn[p] = sqrtf(fmaxf(0.f, 1.f - q * q));
        pfc[p] = 2.f * sfca[j] * sfca[k2];
        // f2_i = exp(-8*(xm - (0.9+0.65i))^2), chained (safe: bounded factors)
        float xm = 0.5f * (d1 + d2);
        float ta = xm - 0.9f;
        float f0 = __expf(-8.f * ta * ta);
        float R  = __expf(10.4f * ta);
        float f1 = f0 * R * 0.0340477f;    // exp(-3.38)
        float f2 = f1 * R * 3.94687e-5f;   // *exp(-10.14)/exp(-3.38) chain const
        float f3 = f2 * R * 4.5755e-8f;
        // note: the chain constants are exp(-3.38*(2i+1)) ratios:
        // f1=f0*R*e^-3.38, f2=f1*R*e^-10.14, f3=f2*R*e^-16.9 -> fix below
        f2 = f1 * R * 3.94687e-5f / 0.0340477f;  // placeholder avoided; see exact below
        // exact chained form:
        f1 = f0 * R * 0.0340477f;                // e^-3.38
        f2 = f1 * R * 3.94687e-5f / 3.94687e-5f * 3.94687e-5f; // keep exact consts
        f2 = f1 * R * 3.94687e-5f * (1.0f / 0.0340477f) * 0.0340477f;
        // (simplify: u_i = R * exp(-3.38*(2i+1)))
        f1 = f0 * R * 0.0340477f;     // u_0 = R*e^-3.38
        f2 = f1 * R * 3.94687e-5f;    // u_1 = R*e^-10.14
        f3 = f2 * R * 4.5755e-8f;     // u_2 = R*e^-16.9
        pf2[0][p] = f0; pf2[1][p] = f1; pf2[2][p] = f2; pf2[3][p] = f3;
        ppi[p] = c_triu[sspec[j] * 4 + sspec[k2]];
    }
    __syncthreads();

    // ---- angular stage 2: features x pair-chunks, register bucket accum ----
    {
        int f  = tid & 31, ch = tid >> 5;
        int z  = f >> 2,  i4 = f & 3;
        float cz = c_cz[z], sz = c_sz[z];
        float acc[NPAIR];
        #pragma unroll
        for (int u = 0; u < NPAIR; u++) acc[u] = 0.f;
        int p0 = ch * 69, p1 = p0 + 69;   // 276 = 4*69
        for (int p = p0; p < p1; p++) {
            float q = pq[p], sn = psn[p];
            float cd = fmaf(q, cz, sn * sz);
            float b  = 0.5f + 0.5f * cd;
            float b2 = b * b, b4 = b2 * b2, b8 = b4 * b4, b16 = b8 * b8, b32 = b16 * b16;
            float val = b32 * pf2[i4][p] * pfc[p];
            int pi = ppi[p];
            #pragma unroll
            for (int u = 0; u < NPAIR; u++) acc[u] += (u == pi) ? val : 0.f;
        }
        #pragma unroll
        for (int u = 0; u < NPAIR; u++) ascr[ch][u][f] = acc[u];
    }
    __syncthreads();

    for (int t = tid; t < NPAIR * 32; t += 128) {
        int pp = t >> 5, ff = t & 31;
        aev[RAD + pp * 32 + ff] =
            ascr[0][pp][ff] + ascr[1][pp][ff] + ascr[2][pp][ff] + ascr[3][pp][ff];
    }
    __syncthreads();

    for (int t = tid; t < AEVDIM; t += 128) g_aev[id * AEVDIM + t] = aev[t];
}

// ---------------------------------------------------------------------------
// Kernel 2: per-species MLP, one block (256 threads) per molecule.
// ---------------------------------------------------------------------------
#define TFK 32

template<int FIN, int FOUT, int ISTR, int OSTR>
__device__ __forceinline__ void mlp_layer(
    const float* __restrict__ Wg, const float* __restrict__ bg,
    const float* in_sh, float* out_sh, float* wt,
    const int* off, const int* cnt)
{
    const int tid = threadIdx.x;
    const int to  = tid & 31;
    const int ta  = tid >> 5;      // warp id == row group (uniform per warp)
    constexpr int NO = FOUT / 32;

    for (int s = 0; s < SS; s++) {
        int m = cnt[s];
        if (m == 0) continue;
        int roff = off[s];
        const float* W = Wg + s * FIN * FOUT;

        float acc[NO][8];
        #pragma unroll
        for (int jo = 0; jo < NO; jo++)
            #pragma unroll
            for (int jr = 0; jr < 8; jr++) acc[jo][jr] = 0.f;

        for (int f0 = 0; f0 < FIN; f0 += TFK) {
            __syncthreads();
            const float4* src = reinterpret_cast<const float4*>(W + f0 * FOUT);
            float4* dst = reinterpret_cast<float4*>(wt);
            for (int idx = tid; idx < TFK * FOUT / 4; idx += 256) dst[idx] = src[idx];
            __syncthreads();

            for (int ff = 0; ff < TFK; ff++) {
                float wv[NO];
                #pragma unroll
                for (int jo = 0; jo < NO; jo++) wv[jo] = wt[ff * FOUT + to + 32 * jo];
                #pragma unroll
                for (int jr = 0; jr < 8; jr++) {
                    int r = ta + 8 * jr;
                    if (r < m) {    // warp-uniform -> branches away, not predicates
                        float iv = in_sh[(roff + r) * ISTR + f0 + ff];
                        #pragma unroll
                        for (int jo = 0; jo < NO; jo++)
                            acc[jo][jr] = fmaf(iv, wv[jo], acc[jo][jr]);
                    }
                }
            }
        }
        // epilogue: bias + CELU(0.1)
        #pragma unroll
        for (int jr = 0; jr < 8; jr++) {
            int r = ta + 8 * jr;
            if (r < m) {
                #pragma unroll
                for (int jo = 0; jo < NO; jo++) {
                    int o = to + 32 * jo;
                    float v = acc[jo][jr] + bg[s * FOUT + o];
                    v = (v > 0.f) ? v : 0.1f * (__expf(v * 10.f) - 1.f);
                    out_sh[(roff + r) * OSTR + o] = v;
                }
            }
        }
    }
    __syncthreads();
}

extern __shared__ float dynsm[];

__global__ __launch_bounds__(256, 1) void mlp_kernel(
    const int* __restrict__ elem,
    const float* __restrict__ W1, const float* __restrict__ b1,
    const float* __restrict__ W2, const float* __restrict__ b2,
    const float* __restrict__ W3, const float* __restrict__ b3,
    const float* __restrict__ W4, const float* __restrict__ b4,
    float* __restrict__ out)
{
    float* inbuf = dynsm;                     // 64*384, reused as h2 (64*128)
    float* bufB  = dynsm + AA * AEVDIM;       // h1 (64*160), reused as h3 (64*97)
    float* wt    = bufB + AA * 160;           // 32*160 weight tile

    __shared__ int spc[AA], perm[AA], rowspec[AA], off[SS + 1], cnt[SS], cur[SS];
    __shared__ float energy[AA];

    const int c = blockIdx.x, tid = threadIdx.x;

    if (tid < SS) { cnt[tid] = 0; cur[tid] = 0; }
    __syncthreads();
    if (tid < AA) { int s = elem[c * AA + tid]; spc[tid] = s; atomicAdd(&cnt[s], 1); }
    __syncthreads();
    if (tid == 0) {
        off[0] = 0;
        for (int s = 0; s < SS; s++) off[s + 1] = off[s] + cnt[s];
    }
    __syncthreads();
    if (tid < AA) {
        int s = spc[tid];
        int pos = off[s] + atomicAdd(&cur[s], 1);
        perm[pos] = tid; rowspec[pos] = s;
    }
    __syncthreads();

    // load AEVs in species-sorted row order
    for (int idx = tid; idx < AA * AEVDIM; idx += 256) {
        int r = idx / AEVDIM, ff = idx - r * AEVDIM;
        inbuf[r * AEVDIM + ff] = g_aev[(c * AA + perm[r]) * AEVDIM + ff];
    }
    __syncthreads();

    mlp_layer<384, 160, 384, 160>(W1, b1, inbuf, bufB,  wt, off, cnt);
    mlp_layer<160, 128, 160, 128>(W2, b2, bufB,  inbuf, wt, off, cnt);
    mlp_layer<128,  96, 128,  97>(W3, b3, inbuf, bufB,  wt, off, cnt);

    // layer 4: 96 -> 1 (stride 97 keeps this conflict-free)
    if (tid < AA) {
        int s = rowspec[tid];
        const float* w = W4 + s * 96;
        float a = 0.f;
        #pragma unroll 8
        for (int ff = 0; ff < 96; ff++) a = fmaf(bufB[tid * 97 + ff], w[ff], a);
        energy[tid] = a + b4[s];
    }
    __syncthreads();
    if (tid < 32) {
        float v = energy[tid] + energy[tid + 32];
        #pragma unroll
        for (int o = 16; o; o >>= 1) v += __shfl_down_sync(0xffffffffu, v, o);
        if (tid == 0) out[c] = v;
    }
}

// ---------------------------------------------------------------------------
extern "C" void kernel_launch(void* const* d_in, const int* in_sizes, int n_in,
                              void* d_out, int out_size)
{
    const int*   elem = (const int*)d_in[0];
    const int*   nbr  = (const int*)d_in[1];
    const float* dist = (const float*)d_in[2];
    const float* diff = (const float*)d_in[3];
    const float* W1 = (const float*)d_in[4],  *b1 = (const float*)d_in[5];
    const float* W2 = (const float*)d_in[6],  *b2 = (const float*)d_in[7];
    const float* W3 = (const float*)d_in[8],  *b3 = (const float*)d_in[9];
    const float* W4 = (const float*)d_in[10], *b4 = (const float*)d_in[11];
    float* out = (float*)d_out;

    const int dyn = (AA * AEVDIM + AA * 160 + TFK * 160) * (int)sizeof(float); // 159744
    cudaFuncSetAttribute(mlp_kernel, cudaFuncAttributeMaxDynamicSharedMemorySize, dyn);

    aev_kernel<<<CC * AA, 128>>>(elem, nbr, dist, diff);
    mlp_kernel<<<CC, 256, dyn>>>(elem, W1, b1, W2, b2, W3, b3, W4, b4, out);
}

// round 2
// speedup vs baseline: 1.8070x; 1.8070x over previous
#include <cuda_runtime.h>

#define CC 128
#define AA 64
#define KN 24
#define SS 4
#define NP 276        // 24*23/2
#define NPAIR 10
#define AEVDIM 384
#define RAD 64
#define NATOM (CC*AA)

// ---- global scratch (no allocs allowed) ----
__device__ float g_x0[NATOM * 384];   // sorted AEVs
__device__ float g_h1[NATOM * 160];
__device__ float g_h2[NATOM * 128];
__device__ float g_h3[NATOM * 96];
__device__ int   g_sortpos[NATOM];    // atom id -> sorted row
__device__ int   g_off[SS], g_cnt[SS];

__constant__ int c_triu[16] = {0,1,2,3, 1,4,5,6, 2,5,7,8, 3,6,8,9};
__constant__ float c_cz[8] = { 0.98078528f, 0.83146961f, 0.55557023f, 0.19509032f,
                              -0.19509032f,-0.55557023f,-0.83146961f,-0.98078528f};
__constant__ float c_sz[8] = { 0.19509032f, 0.55557023f, 0.83146961f, 0.98078528f,
                               0.98078528f, 0.83146961f, 0.55557023f, 0.19509032f};

// ---------------------------------------------------------------------------
// Kernel 0: global species sort (single CTA, 256 threads, 32 atoms each)
// ---------------------------------------------------------------------------
__global__ __launch_bounds__(256) void sort_kernel(const int* __restrict__ elem)
{
    __shared__ int tot[SS], off[SS];
    const int tid = threadIdx.x;
    if (tid < SS) tot[tid] = 0;
    __syncthreads();

    int sp[32];
    int lc[SS] = {0,0,0,0};
    const int base = tid * 32;
    #pragma unroll
    for (int i = 0; i < 32; i++) { int s = elem[base + i]; sp[i] = s; lc[s]++; }

    int bas[SS];
    #pragma unroll
    for (int s = 0; s < SS; s++) bas[s] = atomicAdd(&tot[s], lc[s]);
    __syncthreads();

    if (tid == 0) {
        int o = 0;
        for (int s = 0; s < SS; s++) { off[s] = o; g_off[s] = o; g_cnt[s] = tot[s]; o += tot[s]; }
    }
    __syncthreads();

    #pragma unroll
    for (int i = 0; i < 32; i++) {
        int s = sp[i];
        g_sortpos[base + i] = off[s] + bas[s]++;
    }
}

// ---------------------------------------------------------------------------
// Kernel 1: AEV per atom (one 128-thread block per atom), writes sorted row
// ---------------------------------------------------------------------------
__global__ __launch_bounds__(128) void aev_kernel(
    const int* __restrict__ elem, const int* __restrict__ nbr,
    const float* __restrict__ dist, const float* __restrict__ diff)
{
    const int id  = blockIdx.x;      // c*64 + a
    const int c   = id >> 6;
    const int tid = threadIdx.x;

    __shared__ float sd[KN], sfca[KN];
    __shared__ float su[KN][3];
    __shared__ int   sspec[KN];
    __shared__ float aev[AEVDIM];
    __shared__ float pq[NP], psn[NP], pfc[NP];
    __shared__ float pf2[4][NP];
    __shared__ int   ppi[NP];
    __shared__ float ascr[4][NPAIR][32];
    __shared__ int   srow;

    if (tid == 0) srow = g_sortpos[id];

    float my_fcr = 0.f;
    if (tid < KN) {
        float d = dist[id * KN + tid];
        sd[tid] = d;
        const float PI = 3.14159265358979f;
        my_fcr     = (d < 5.2f) ? (0.5f * __cosf(PI * d / 5.2f) + 0.5f) : 0.f;
        sfca[tid]  = (d < 3.5f) ? (0.5f * __cosf(PI * d / 3.5f) + 0.5f) : 0.f;
        float inv = 1.0f / d;
        su[tid][0] = diff[(id * KN + tid) * 3 + 0] * inv;
        su[tid][1] = diff[(id * KN + tid) * 3 + 1] * inv;
        su[tid][2] = diff[(id * KN + tid) * 3 + 2] * inv;
        sspec[tid] = elem[c * AA + nbr[id * KN + tid]];
    }
    for (int t = tid; t < AEVDIM; t += 128) aev[t] = 0.f;
    __syncthreads();

    // ---- radial: chained exp factors from the nearest shift ----
    if (tid < KN) {
        float d     = sd[tid];
        int   sp    = sspec[tid];
        float scale = 0.25f * my_fcr;
        float t     = d - 0.9f;
        int istar = __float2int_rn(t * 3.7209302f);
        istar = max(0, min(15, istar));
        float ds  = t - 0.26875f * (float)istar;
        float epk = __expf(-16.f * ds * ds);
        const float WW = 0.09913725f;                  // exp(-2*1.155625)
        float e = epk;
        float w = __expf(8.6f * t - 1.155625f * (2.f * istar + 1.f));
        for (int r = istar; r < 16; r++) {
            atomicAdd(&aev[sp * 16 + r], scale * e);
            e *= w; w *= WW;
        }
        e = epk;
        w = __expf(-8.6f * t + 1.155625f * (2.f * istar - 1.f));
        for (int r = istar - 1; r >= 0; r--) {
            e *= w; w *= WW;
            atomicAdd(&aev[sp * 16 + r], scale * e);
        }
    }

    // ---- angular stage 1: per-pair quantities ----
    for (int p = tid; p < NP; p += 128) {
        int j = 0, rem = p;
        while (rem >= KN - 1 - j) { rem -= KN - 1 - j; j++; }
        int k2 = j + 1 + rem;

        float d1 = sd[j], d2 = sd[k2];
        float dot = su[j][0]*su[k2][0] + su[j][1]*su[k2][1] + su[j][2]*su[k2][2];
        float q = 0.95f * dot;
        pq[p]  = q;
        psn[p] = sqrtf(fmaxf(0.f, 1.f - q * q));
        pfc[p] = 2.f * sfca[j] * sfca[k2];
        float xm = 0.5f * (d1 + d2);
        float ta = xm - 0.9f;
        float f0 = __expf(-8.f * ta * ta);
        float R  = __expf(10.4f * ta);
        float f1 = f0 * R * 0.0340477f;     // * exp(-3.38)
        float f2 = f1 * R * 3.94687e-5f;    // * exp(-10.14)
        float f3 = f2 * R * 4.5755e-8f;     // * exp(-16.9)
        pf2[0][p] = f0; pf2[1][p] = f1; pf2[2][p] = f2; pf2[3][p] = f3;
        ppi[p] = c_triu[sspec[j] * 4 + sspec[k2]];
    }
    __syncthreads();

    // ---- angular stage 2 ----
    {
        int f  = tid & 31, ch = tid >> 5;
        int z  = f >> 2,  i4 = f & 3;
        float cz = c_cz[z], sz = c_sz[z];
        float acc[NPAIR];
        #pragma unroll
        for (int u = 0; u < NPAIR; u++) acc[u] = 0.f;
        int p0 = ch * 69, p1 = p0 + 69;
        for (int p = p0; p < p1; p++) {
            float q = pq[p], sn = psn[p];
            float cd = fmaf(q, cz, sn * sz);
            float b  = 0.5f + 0.5f * cd;
            float b2 = b * b, b4 = b2 * b2, b8 = b4 * b4, b16 = b8 * b8, b32 = b16 * b16;
            float val = b32 * pf2[i4][p] * pfc[p];
            int pi = ppi[p];
            #pragma unroll
            for (int u = 0; u < NPAIR; u++) acc[u] += (u == pi) ? val : 0.f;
        }
        #pragma unroll
        for (int u = 0; u < NPAIR; u++) ascr[ch][u][f] = acc[u];
    }
    __syncthreads();

    for (int t = tid; t < NPAIR * 32; t += 128) {
        int pp = t >> 5, ff = t & 31;
        aev[RAD + pp * 32 + ff] =
            ascr[0][pp][ff] + ascr[1][pp][ff] + ascr[2][pp][ff] + ascr[3][pp][ff];
    }
    __syncthreads();

    const int row = srow;
    for (int t = tid; t < AEVDIM; t += 128) g_x0[row * AEVDIM + t] = aev[t];
}

// ---------------------------------------------------------------------------
// GEMM + CELU layer: 64 sorted rows x FOUT per CTA, one species per CTA.
// Thread tile: 8 rows x NO cols. grid = (128, SS).
// ---------------------------------------------------------------------------
template<int L>
__global__ __launch_bounds__(256) void gemm_celu(
    const float* __restrict__ Wg, const float* __restrict__ bg)
{
    constexpr int FIN  = (L==1)?384 : (L==2)?160 : 128;
    constexpr int FOUT = (L==1)?160 : (L==2)?128 : 96;
    constexpr int NO   = FOUT / 32;
    const float* X = (L==1)? g_x0 : (L==2)? g_h1 : g_h2;
    float*       Y = (L==1)? g_h1 : (L==2)? g_h2 : g_h3;

    __shared__ float a_sh[64 * 36];          // [row][k] pad 36
    __shared__ float w_sh[32 * FOUT];        // [k][col]

    const int s    = blockIdx.y;
    const int cnt  = g_cnt[s];
    const int rb   = blockIdx.x * 64;
    if (rb >= cnt) return;
    const int m    = cnt - rb;               // valid rows (<=64)
    const int off  = g_off[s];
    const float* W = Wg + s * FIN * FOUT;

    const int tid = threadIdx.x, tx = tid & 31, ty = tid >> 5;

    float acc[8][NO];
    #pragma unroll
    for (int i = 0; i < 8; i++)
        #pragma unroll
        for (int jo = 0; jo < NO; jo++) acc[i][jo] = 0.f;

    for (int f0 = 0; f0 < FIN; f0 += 32) {
        __syncthreads();
        // stage A: 64 rows x 32 k (clamp rows to stay inside this species)
        #pragma unroll
        for (int i = tid; i < 64 * 8; i += 256) {
            int row = i >> 3, k4 = i & 7;
            int rg  = off + rb + min(row, m - 1);
            float4 v = *reinterpret_cast<const float4*>(&X[rg * FIN + f0 + k4 * 4]);
            *reinterpret_cast<float4*>(&a_sh[row * 36 + k4 * 4]) = v;
        }
        // stage W: 32 x FOUT
        const float4* wsrc = reinterpret_cast<const float4*>(W + f0 * FOUT);
        #pragma unroll
        for (int i = tid; i < 32 * FOUT / 4; i += 256)
            reinterpret_cast<float4*>(w_sh)[i] = wsrc[i];
        __syncthreads();

        #pragma unroll
        for (int kk = 0; kk < 32; kk++) {
            float wv[NO];
            #pragma unroll
            for (int jo = 0; jo < NO; jo++) wv[jo] = w_sh[kk * FOUT + tx + 32 * jo];
            #pragma unroll
            for (int i = 0; i < 8; i++) {
                float av = a_sh[(ty * 8 + i) * 36 + kk];   // warp-broadcast
                #pragma unroll
                for (int jo = 0; jo < NO; jo++)
                    acc[i][jo] = fmaf(av, wv[jo], acc[i][jo]);
            }
        }
    }

    // epilogue: bias + CELU(0.1)
    #pragma unroll
    for (int i = 0; i < 8; i++) {
        int r = ty * 8 + i;
        if (r < m) {
            int rg = off + rb + r;
            #pragma unroll
            for (int jo = 0; jo < NO; jo++) {
                int o = tx + 32 * jo;
                float v = acc[i][jo] + bg[s * FOUT + o];
                v = (v > 0.f) ? v : 0.1f * (__expf(v * 10.f) - 1.f);
                Y[rg * FOUT + o] = v;
            }
        }
    }
}

// ---------------------------------------------------------------------------
// Final: layer4 (96 -> 1) + per-molecule sum. One 64-thread CTA per molecule.
// ---------------------------------------------------------------------------
__global__ __launch_bounds__(64) void final_kernel(
    const int* __restrict__ elem,
    const float* __restrict__ W4, const float* __restrict__ b4,
    float* __restrict__ out)
{
    const int c = blockIdx.x, a = threadIdx.x;
    __shared__ float e[AA];

    const int row = g_sortpos[c * AA + a];
    const int s   = elem[c * AA + a];
    const float* h = &g_h3[row * 96];
    const float* w = &W4[s * 96];
    float acc = 0.f;
    #pragma unroll
    for (int f = 0; f < 96; f += 4) {
        float4 hv = *reinterpret_cast<const float4*>(h + f);
        float4 wv = *reinterpret_cast<const float4*>(w + f);
        acc = fmaf(hv.x, wv.x, acc);
        acc = fmaf(hv.y, wv.y, acc);
        acc = fmaf(hv.z, wv.z, acc);
        acc = fmaf(hv.w, wv.w, acc);
    }
    e[a] = acc + b4[s];
    __syncthreads();
    if (a < 32) {
        float v = e[a] + e[a + 32];
        #pragma unroll
        for (int o = 16; o; o >>= 1) v += __shfl_down_sync(0xffffffffu, v, o);
        if (a == 0) out[c] = v;
    }
}

// ---------------------------------------------------------------------------
extern "C" void kernel_launch(void* const* d_in, const int* in_sizes, int n_in,
                              void* d_out, int out_size)
{
    const int*   elem = (const int*)d_in[0];
    const int*   nbr  = (const int*)d_in[1];
    const float* dist = (const float*)d_in[2];
    const float* diff = (const float*)d_in[3];
    const float* W1 = (const float*)d_in[4],  *b1 = (const float*)d_in[5];
    const float* W2 = (const float*)d_in[6],  *b2 = (const float*)d_in[7];
    const float* W3 = (const float*)d_in[8],  *b3 = (const float*)d_in[9];
    const float* W4 = (const float*)d_in[10], *b4 = (const float*)d_in[11];
    float* out = (float*)d_out;

    sort_kernel<<<1, 256>>>(elem);
    aev_kernel<<<NATOM, 128>>>(elem, nbr, dist, diff);
    dim3 g(128, SS);
    gemm_celu<1><<<g, 256>>>(W1, b1);
    gemm_celu<2><<<g, 256>>>(W2, b2);
    gemm_celu<3><<<g, 256>>>(W3, b3);
    final_kernel<<<CC, 64>>>(elem, W4, b4, out);
}

// round 4
// speedup vs baseline: 2.0915x; 1.1574x over previous
#include <cuda_runtime.h>

#define CC 128
#define AA 64
#define KN 24
#define SS 4
#define NP 276        // 24*23/2
#define NPAIR 10
#define AEVDIM 384
#define RAD 64
#define NATOM (CC*AA)
#define NSL 12        // slices per bucket in angular stage 2

// ---- global scratch (no allocs allowed) ----
__device__ __align__(16) float g_x0[NATOM * AEVDIM];   // sorted AEVs
__device__ __align__(16) float g_e[NATOM];             // per-sorted-row energy
__device__ __align__(16) float g_w1T[SS * 160 * 384];
__device__ __align__(16) float g_w2T[SS * 128 * 160];
__device__ __align__(16) float g_w3T[SS * 96 * 128];
__device__ int g_sortpos[NATOM];
__device__ int g_off[SS], g_cnt[SS];

__constant__ int c_triu[16] = {0,1,2,3, 1,4,5,6, 2,5,7,8, 3,6,8,9};
__constant__ float c_cz[8] = { 0.98078528f, 0.83146961f, 0.55557023f, 0.19509032f,
                              -0.19509032f,-0.55557023f,-0.83146961f,-0.98078528f};
__constant__ float c_sz[8] = { 0.19509032f, 0.55557023f, 0.83146961f, 0.98078528f,
                               0.98078528f, 0.83146961f, 0.55557023f, 0.19509032f};

// ---------------------------------------------------------------------------
// Kernel 0a: global species sort (single CTA)
// ---------------------------------------------------------------------------
__global__ __launch_bounds__(256) void sort_kernel(const int* __restrict__ elem)
{
    __shared__ int tot[SS], off[SS];
    const int tid = threadIdx.x;
    if (tid < SS) tot[tid] = 0;
    __syncthreads();

    int sp[32];
    int lc[SS] = {0,0,0,0};
    const int base = tid * 32;
    #pragma unroll
    for (int i = 0; i < 32; i++) { int s = elem[base + i]; sp[i] = s; lc[s]++; }

    int bas[SS];
    #pragma unroll
    for (int s = 0; s < SS; s++) bas[s] = atomicAdd(&tot[s], lc[s]);
    __syncthreads();

    if (tid == 0) {
        int o = 0;
        for (int s = 0; s < SS; s++) { off[s] = o; g_off[s] = o; g_cnt[s] = tot[s]; o += tot[s]; }
    }
    __syncthreads();

    #pragma unroll
    for (int i = 0; i < 32; i++) {
        int s = sp[i];
        g_sortpos[base + i] = off[s] + bas[s]++;
    }
}

// ---------------------------------------------------------------------------
// Kernel 0b: weight transpose  W[s][f][o] -> wT[s][o][f]
// ---------------------------------------------------------------------------
__global__ __launch_bounds__(256) void wT_kernel(
    const float* __restrict__ W1, const float* __restrict__ W2, const float* __restrict__ W3)
{
    const int stride = gridDim.x * blockDim.x;
    int i0 = blockIdx.x * blockDim.x + threadIdx.x;
    for (int idx = i0; idx < SS * 384 * 160; idx += stride) {
        int s = idx / (384 * 160); int r = idx - s * 384 * 160;
        int f = r / 160, o = r - f * 160;
        g_w1T[(s * 160 + o) * 384 + f] = W1[idx];
    }
    for (int idx = i0; idx < SS * 160 * 128; idx += stride) {
        int s = idx / (160 * 128); int r = idx - s * 160 * 128;
        int f = r / 128, o = r - f * 128;
        g_w2T[(s * 128 + o) * 160 + f] = W2[idx];
    }
    for (int idx = i0; idx < SS * 128 * 96; idx += stride) {
        int s = idx / (128 * 96); int r = idx - s * 128 * 96;
        int f = r / 96, o = r - f * 96;
        g_w3T[(s * 96 + o) * 128 + f] = W3[idx];
    }
}

// ---------------------------------------------------------------------------
// Kernel 1: AEV per atom. One 128-thread block per atom.
// Angular pairs are bucket-sorted by pair-species, then stage 2 is pair-major.
// ---------------------------------------------------------------------------
__global__ __launch_bounds__(128) void aev_kernel(
    const int* __restrict__ elem, const int* __restrict__ nbr,
    const float* __restrict__ dist, const float* __restrict__ diff)
{
    const int id  = blockIdx.x;      // c*64 + a
    const int c   = id >> 6;
    const int tid = threadIdx.x;

    __shared__ __align__(16) float sd[KN], sfca[KN];
    __shared__ __align__(16) float su[KN][3];
    __shared__ int   sspec[KN];
    __shared__ __align__(16) float aev_r[RAD];
    // unsorted pair data
    __shared__ __align__(16) float uq[NP], usn[NP], ug[4][NP];
    __shared__ int   upi[NP];
    // sorted pair data
    __shared__ __align__(16) float sq[NP], ssn[NP], sg[4][NP];
    __shared__ int   bcnt[NPAIR], boff[NPAIR + 1];
    __shared__ __align__(16) float ascr[NPAIR][NSL][36];
    __shared__ int   srow;

    if (tid == 0) srow = g_sortpos[id];
    if (tid < NPAIR) bcnt[tid] = 0;

    float my_fcr = 0.f;
    if (tid < KN) {
        float d = dist[id * KN + tid];
        sd[tid] = d;
        const float PI = 3.14159265358979f;
        my_fcr     = (d < 5.2f) ? (0.5f * __cosf(PI * d / 5.2f) + 0.5f) : 0.f;
        sfca[tid]  = (d < 3.5f) ? (0.5f * __cosf(PI * d / 3.5f) + 0.5f) : 0.f;
        float inv = 1.0f / d;
        su[tid][0] = diff[(id * KN + tid) * 3 + 0] * inv;
        su[tid][1] = diff[(id * KN + tid) * 3 + 1] * inv;
        su[tid][2] = diff[(id * KN + tid) * 3 + 2] * inv;
        sspec[tid] = elem[c * AA + nbr[id * KN + tid]];
    }
    if (tid < RAD) aev_r[tid] = 0.f;
    __syncthreads();

    // ---- radial: chained exp factors from the nearest shift ----
    if (tid < KN) {
        float d     = sd[tid];
        int   sp    = sspec[tid];
        float scale = 0.25f * my_fcr;
        float t     = d - 0.9f;
        int istar = __float2int_rn(t * 3.7209302f);
        istar = max(0, min(15, istar));
        float ds  = t - 0.26875f * (float)istar;
        float epk = __expf(-16.f * ds * ds);
        const float WW = 0.09913725f;                  // exp(-2*1.155625)
        float e = epk;
        float w = __expf(8.6f * t - 1.155625f * (2.f * istar + 1.f));
        for (int r = istar; r < 16; r++) {
            atomicAdd(&aev_r[sp * 16 + r], scale * e);
            e *= w; w *= WW;
        }
        e = epk;
        w = __expf(-8.6f * t + 1.155625f * (2.f * istar - 1.f));
        for (int r = istar - 1; r >= 0; r--) {
            e *= w; w *= WW;
            atomicAdd(&aev_r[sp * 16 + r], scale * e);
        }
    }

    // ---- angular stage 1: per-pair quantities + bucket counts ----
    for (int p = tid; p < NP; p += 128) {
        int j = 0, rem = p;
        while (rem >= KN - 1 - j) { rem -= KN - 1 - j; j++; }
        int k2 = j + 1 + rem;

        float d1 = sd[j], d2 = sd[k2];
        float dot = su[j][0]*su[k2][0] + su[j][1]*su[k2][1] + su[j][2]*su[k2][2];
        float q = 0.95f * dot;
        uq[p]  = q;
        usn[p] = sqrtf(fmaxf(0.f, 1.f - q * q));
        float fc12 = 2.f * sfca[j] * sfca[k2];
        float xm = 0.5f * (d1 + d2);
        float ta = xm - 0.9f;
        float f0 = __expf(-8.f * ta * ta);
        float R  = __expf(10.4f * ta);
        float f1 = f0 * R * 0.0340475f;     // * exp(-3.38)
        float f2 = f1 * R * 3.94688e-5f;    // * exp(-10.14)
        float f3 = f2 * R * 4.57533e-8f;    // * exp(-16.9)
        ug[0][p] = f0 * fc12; ug[1][p] = f1 * fc12;
        ug[2][p] = f2 * fc12; ug[3][p] = f3 * fc12;
        int pi = c_triu[sspec[j] * 4 + sspec[k2]];
        upi[p] = pi;
        atomicAdd(&bcnt[pi], 1);
    }
    __syncthreads();

    if (tid == 0) {
        int o = 0;
        #pragma unroll
        for (int u = 0; u < NPAIR; u++) { boff[u] = o; o += bcnt[u]; bcnt[u] = boff[u]; }
        boff[NPAIR] = o;
    }
    __syncthreads();

    // scatter into sorted arrays (order within bucket irrelevant)
    for (int p = tid; p < NP; p += 128) {
        int pos = atomicAdd(&bcnt[upi[p]], 1);
        sq[pos]  = uq[p];
        ssn[pos] = usn[p];
        sg[0][pos] = ug[0][p]; sg[1][pos] = ug[1][p];
        sg[2][pos] = ug[2][p]; sg[3][pos] = ug[3][p];
    }
    __syncthreads();

    // ---- angular stage 2: pair-major, 10 buckets x 12 slices ----
    if (tid < NPAIR * NSL) {
        const int u  = tid / NSL;
        const int sl = tid - u * NSL;
        float lcz[8], lsz[8];
        #pragma unroll
        for (int z = 0; z < 8; z++) { lcz[z] = c_cz[z]; lsz[z] = c_sz[z]; }

        float acc[32];
        #pragma unroll
        for (int f = 0; f < 32; f++) acc[f] = 0.f;

        const int e0 = boff[u], e1 = boff[u + 1];
        for (int idx = e0 + sl; idx < e1; idx += NSL) {
            float q  = sq[idx], sn = ssn[idx];
            float g0 = sg[0][idx], g1 = sg[1][idx], g2 = sg[2][idx], g3 = sg[3][idx];
            #pragma unroll
            for (int z = 0; z < 8; z++) {
                float cd  = fmaf(q, lcz[z], sn * lsz[z]);
                float b   = fmaf(cd, 0.5f, 0.5f);
                float b2 = b*b, b4 = b2*b2, b8 = b4*b4, b16 = b8*b8, b32 = b16*b16;
                acc[z*4+0] = fmaf(b32, g0, acc[z*4+0]);
                acc[z*4+1] = fmaf(b32, g1, acc[z*4+1]);
                acc[z*4+2] = fmaf(b32, g2, acc[z*4+2]);
                acc[z*4+3] = fmaf(b32, g3, acc[z*4+3]);
            }
        }
        #pragma unroll
        for (int f = 0; f < 32; f += 4)
            *reinterpret_cast<float4*>(&ascr[u][sl][f]) =
                make_float4(acc[f], acc[f+1], acc[f+2], acc[f+3]);
    }
    __syncthreads();

    // ---- write AEV row to global (sorted position) ----
    const int row = srow;
    if (tid < RAD) g_x0[row * AEVDIM + tid] = aev_r[tid];
    for (int t = tid; t < NPAIR * 32; t += 128) {
        int u = t >> 5, f = t & 31;
        float s = 0.f;
        #pragma unroll
        for (int sl = 0; sl < NSL; sl++) s += ascr[u][sl][f];
        g_x0[row * AEVDIM + RAD + t] = s;
    }
}

// ---------------------------------------------------------------------------
// Fused MLP: one CTA = 64 sorted rows of one species, all layers in smem.
// ---------------------------------------------------------------------------
#define A_SH_F (64 * 36)
#define W_SH_F (160 * 36)
#define H1_F   (64 * 164)
#define H2_F   (64 * 132)
#define DYN_F  (A_SH_F + W_SH_F + H1_F + H2_F)

extern __shared__ float dynsm[];

template<int FIN, int FOUT, int ISTR, int OSTR, bool FROMG>
__device__ __forceinline__ void layerf(
    const float* __restrict__ wT,    // [FOUT][FIN] for this species
    const float* __restrict__ bias,  // [FOUT]
    const float* __restrict__ gin,   // global rows base (FROMG)
    const float* __restrict__ in,    // smem input rows (!FROMG)
    float* __restrict__ out,         // smem output rows
    float* a_sh, float* w_sh, int m)
{
    const int tid = threadIdx.x, tx = tid & 31, ty = tid >> 5;
    constexpr int NO = FOUT / 32;

    float acc[8][NO];
    #pragma unroll
    for (int i = 0; i < 8; i++)
        #pragma unroll
        for (int jo = 0; jo < NO; jo++) acc[i][jo] = 0.f;

    for (int f0 = 0; f0 < FIN; f0 += 32) {
        __syncthreads();
        if (FROMG) {
            #pragma unroll
            for (int i = tid; i < 64 * 8; i += 256) {
                int r = i >> 3, k4 = i & 7;
                int rg = min(r, m - 1);
                float4 v = *reinterpret_cast<const float4*>(&gin[rg * FIN + f0 + k4 * 4]);
                *reinterpret_cast<float4*>(&a_sh[r * 36 + k4 * 4]) = v;
            }
        }
        #pragma unroll
        for (int i = tid; i < FOUT * 8; i += 256) {
            int col = i >> 3, k4 = i & 7;
            float4 v = *reinterpret_cast<const float4*>(&wT[col * FIN + f0 + k4 * 4]);
            *reinterpret_cast<float4*>(&w_sh[col * 36 + k4 * 4]) = v;
        }
        __syncthreads();

        #pragma unroll
        for (int g = 0; g < 8; g++) {
            float4 wv[NO];
            #pragma unroll
            for (int jo = 0; jo < NO; jo++)
                wv[jo] = *reinterpret_cast<const float4*>(&w_sh[(tx + 32 * jo) * 36 + 4 * g]);
            #pragma unroll
            for (int i = 0; i < 8; i++) {
                float4 av;
                if (FROMG)
                    av = *reinterpret_cast<const float4*>(&a_sh[(ty * 8 + i) * 36 + 4 * g]);
                else
                    av = *reinterpret_cast<const float4*>(&in[(ty * 8 + i) * ISTR + f0 + 4 * g]);
                #pragma unroll
                for (int jo = 0; jo < NO; jo++) {
                    acc[i][jo] = fmaf(av.x, wv[jo].x, acc[i][jo]);
                    acc[i][jo] = fmaf(av.y, wv[jo].y, acc[i][jo]);
                    acc[i][jo] = fmaf(av.z, wv[jo].z, acc[i][jo]);
                    acc[i][jo] = fmaf(av.w, wv[jo].w, acc[i][jo]);
                }
            }
        }
    }

    // epilogue: bias + CELU(0.1)
    #pragma unroll
    for (int i = 0; i < 8; i++) {
        int r = ty * 8 + i;
        if (r < m) {
            #pragma unroll
            for (int jo = 0; jo < NO; jo++) {
                int o = tx + 32 * jo;
                float v = acc[i][jo] + bias[o];
                v = (v > 0.f) ? v : 0.1f * (__expf(v * 10.f) - 1.f);
                out[r * OSTR + o] = v;
            }
        }
    }
}

__global__ __launch_bounds__(256, 1) void fused_mlp(
    const float* __restrict__ b1, const float* __restrict__ b2,
    const float* __restrict__ b3,
    const float* __restrict__ W4, const float* __restrict__ b4)
{
    const int s  = blockIdx.y;
    const int cnt = g_cnt[s];
    const int rb = blockIdx.x * 64;
    if (rb >= cnt) return;
    const int m   = min(64, cnt - rb);
    const int off = g_off[s];

    float* a_sh = dynsm;
    float* w_sh = dynsm + A_SH_F;
    float* h1   = w_sh + W_SH_F;       // stride 164 (reused as h3, stride 100)
    float* h2   = h1 + H1_F;           // stride 132

    const float* gin = g_x0 + (size_t)(off + rb) * AEVDIM;

    layerf<384, 160, 384, 164, true >(g_w1T + s * 160 * 384, b1 + s * 160, gin, h1, h1, a_sh, w_sh, m);
    layerf<160, 128, 164, 132, false>(g_w2T + s * 128 * 160, b2 + s * 128, gin, h1, h2, a_sh, w_sh, m);
    layerf<128,  96, 132, 100, false>(g_w3T + s *  96 * 128, b3 + s *  96, gin, h2, h1, a_sh, w_sh, m);
    __syncthreads();

    // layer 4: 96 -> 1 per row, write per-row energy
    const int tid = threadIdx.x;
    if (tid < m) {
        const float* w4 = W4 + s * 96;
        float a = 0.f;
        #pragma unroll
        for (int f = 0; f < 96; f += 4) {
            float4 hv = *reinterpret_cast<const float4*>(&h1[tid * 100 + f]);
            float4 wv = *reinterpret_cast<const float4*>(&w4[f]);
            a = fmaf(hv.x, wv.x, a);
            a = fmaf(hv.y, wv.y, a);
            a = fmaf(hv.z, wv.z, a);
            a = fmaf(hv.w, wv.w, a);
        }
        g_e[off + rb + tid] = a + b4[s];
    }
}

// ---------------------------------------------------------------------------
// Final: per-molecule sum of atomic energies
// ---------------------------------------------------------------------------
__global__ __launch_bounds__(64) void final_kernel(float* __restrict__ out)
{
    const int c = blockIdx.x, a = threadIdx.x;
    __shared__ float e[AA];
    e[a] = g_e[g_sortpos[c * AA + a]];
    __syncthreads();
    if (a < 32) {
        float v = e[a] + e[a + 32];
        #pragma unroll
        for (int o = 16; o; o >>= 1) v += __shfl_down_sync(0xffffffffu, v, o);
        if (a == 0) out[c] = v;
    }
}

// ---------------------------------------------------------------------------
extern "C" void kernel_launch(void* const* d_in, const int* in_sizes, int n_in,
                              void* d_out, int out_size)
{
    const int*   elem = (const int*)d_in[0];
    const int*   nbr  = (const int*)d_in[1];
    const float* dist = (const float*)d_in[2];
    const float* diff = (const float*)d_in[3];
    const float* W1 = (const float*)d_in[4],  *b1 = (const float*)d_in[5];
    const float* W2 = (const float*)d_in[6],  *b2 = (const float*)d_in[7];
    const float* W3 = (const float*)d_in[8],  *b3 = (const float*)d_in[9];
    const float* W4 = (const float*)d_in[10], *b4 = (const float*)d_in[11];
    float* out = (float*)d_out;

    const int dyn = DYN_F * (int)sizeof(float);   // 108,032 B
    cudaFuncSetAttribute(fused_mlp, cudaFuncAttributeMaxDynamicSharedMemorySize, dyn);

    sort_kernel<<<1, 256>>>(elem);
    wT_kernel<<<296, 256>>>(W1, W2, W3);
    aev_kernel<<<NATOM, 128>>>(elem, nbr, dist, diff);
    dim3 g(128, SS);
    fused_mlp<<<g, 256, dyn>>>(b1, b2, b3, W4, b4);
    final_kernel<<<CC, 64>>>(out);
}

// round 5
// speedup vs baseline: 4.2118x; 2.0138x over previous
#include <cuda_runtime.h>

#define CC 128
#define AA 64
#define KN 24
#define SS 4
#define NP 276        // 24*23/2
#define NPAIR 10
#define AEVDIM 384
#define RAD 64
#define NATOM (CC*AA)
#define NSL 8         // slices per bucket in angular stage 2

// ---- global scratch (no allocs allowed) ----
__device__ __align__(16) float g_x0[NATOM * AEVDIM];   // sorted AEVs
__device__ __align__(16) float g_e[NATOM];             // per-sorted-row energy
__device__ __align__(16) float g_w1T[SS * 160 * 384];
__device__ __align__(16) float g_w2T[SS * 128 * 160];
__device__ __align__(16) float g_w3T[SS * 96 * 128];
__device__ int g_sortpos[NATOM];
__device__ int g_off[SS], g_cnt[SS];

__constant__ int c_triu[16] = {0,1,2,3, 1,4,5,6, 2,5,7,8, 3,6,8,9};
__constant__ float c_cz[8] = { 0.98078528f, 0.83146961f, 0.55557023f, 0.19509032f,
                              -0.19509032f,-0.55557023f,-0.83146961f,-0.98078528f};
__constant__ float c_sz[8] = { 0.19509032f, 0.55557023f, 0.83146961f, 0.98078528f,
                               0.98078528f, 0.83146961f, 0.55557023f, 0.19509032f};

__device__ __forceinline__ float fsqrt_a(float x) {
    float r; asm("sqrt.approx.f32 %0, %1;" : "=f"(r) : "f"(x)); return r;
}

#define BROW(j) (((j) * (47 - (j))) >> 1)   // pairs before row j

// ---------------------------------------------------------------------------
// Kernel 0a: global species sort (single CTA)
// ---------------------------------------------------------------------------
__global__ __launch_bounds__(256) void sort_kernel(const int* __restrict__ elem)
{
    __shared__ int tot[SS], off[SS];
    const int tid = threadIdx.x;
    if (tid < SS) tot[tid] = 0;
    __syncthreads();

    int sp[32];
    int lc[SS] = {0,0,0,0};
    const int base = tid * 32;
    #pragma unroll
    for (int i = 0; i < 32; i++) { int s = elem[base + i]; sp[i] = s; lc[s]++; }

    int bas[SS];
    #pragma unroll
    for (int s = 0; s < SS; s++) bas[s] = atomicAdd(&tot[s], lc[s]);
    __syncthreads();

    if (tid == 0) {
        int o = 0;
        for (int s = 0; s < SS; s++) { off[s] = o; g_off[s] = o; g_cnt[s] = tot[s]; o += tot[s]; }
    }
    __syncthreads();

    #pragma unroll
    for (int i = 0; i < 32; i++) {
        int s = sp[i];
        g_sortpos[base + i] = off[s] + bas[s]++;
    }
}

// ---------------------------------------------------------------------------
// Kernel 0b: weight transpose  W[s][f][o] -> wT[s][o][f]
// ---------------------------------------------------------------------------
__global__ __launch_bounds__(256) void wT_kernel(
    const float* __restrict__ W1, const float* __restrict__ W2, const float* __restrict__ W3)
{
    const int stride = gridDim.x * blockDim.x;
    int i0 = blockIdx.x * blockDim.x + threadIdx.x;
    for (int idx = i0; idx < SS * 384 * 160; idx += stride) {
        int s = idx / (384 * 160); int r = idx - s * 384 * 160;
        int f = r / 160, o = r - f * 160;
        g_w1T[(s * 160 + o) * 384 + f] = W1[idx];
    }
    for (int idx = i0; idx < SS * 160 * 128; idx += stride) {
        int s = idx / (160 * 128); int r = idx - s * 160 * 128;
        int f = r / 128, o = r - f * 128;
        g_w2T[(s * 128 + o) * 160 + f] = W2[idx];
    }
    for (int idx = i0; idx < SS * 128 * 96; idx += stride) {
        int s = idx / (128 * 96); int r = idx - s * 128 * 96;
        int f = r / 96, o = r - f * 96;
        g_w3T[(s * 96 + o) * 128 + f] = W3[idx];
    }
}

// ---------------------------------------------------------------------------
// Kernel 1: AEV per atom. One 128-thread block per atom.
// Active-pair compaction (fc12>0) + separable exponentials + bucket sort.
// ---------------------------------------------------------------------------
__global__ __launch_bounds__(128) void aev_kernel(
    const int* __restrict__ elem, const int* __restrict__ nbr,
    const float* __restrict__ dist, const float* __restrict__ diff)
{
    const int id  = blockIdx.x;      // c*64 + a
    const int c   = id >> 6;
    const int tid = threadIdx.x;

    __shared__ __align__(16) float4 nbA[KN];   // ux, uy, uz, a=(d-0.9)/2
    __shared__ __align__(16) float4 nbB[KN];   // R, fca, specf(unused), E2
    __shared__ int   sspec[KN];
    __shared__ float sfca_[KN];
    __shared__ __align__(16) float aev_r[RAD];
    __shared__ int   plist[NP];
    __shared__ __align__(16) float sq[NP], ssn[NP];
    __shared__ __align__(16) float sg0[NP], sg1[NP], sg2[NP], sg3[NP];
    __shared__ int   bcnt[NPAIR], boff[NPAIR + 1], nact;
    __shared__ __align__(16) float ascr[NPAIR][NSL][36];
    __shared__ int   srow;

    if (tid == 0) { srow = g_sortpos[id]; nact = 0; }
    if (tid < NPAIR) bcnt[tid] = 0;
    if (tid < RAD) aev_r[tid] = 0.f;

    if (tid < KN) {
        float d = dist[id * KN + tid];
        const float PI = 3.14159265358979f;
        float fcr = (d < 5.2f) ? (0.5f * __cosf(PI * d / 5.2f) + 0.5f) : 0.f;
        float fca = (d < 3.5f) ? (0.5f * __cosf(PI * d / 3.5f) + 0.5f) : 0.f;
        float inv = 1.0f / d;
        float ux = diff[(id * KN + tid) * 3 + 0] * inv;
        float uy = diff[(id * KN + tid) * 3 + 1] * inv;
        float uz = diff[(id * KN + tid) * 3 + 2] * inv;
        int   sp = elem[c * AA + nbr[id * KN + tid]];
        float a  = 0.5f * d - 0.45f;
        float E2 = __expf(-8.f * a * a);
        float R  = __expf(10.4f * a);
        nbA[tid] = make_float4(ux, uy, uz, a);
        nbB[tid] = make_float4(R, fca, 0.f, E2);
        sspec[tid] = sp;
        sfca_[tid] = fca;

        // radial, windowed +-3 shifts around the nearest one
        float scale = 0.25f * fcr;
        float t     = d - 0.9f;
        int istar = __float2int_rn(t * 3.7209302f);
        istar = max(0, min(15, istar));
        int rlo = max(0, istar - 3), rhi = min(15, istar + 3);
        float ds  = t - 0.26875f * (float)istar;
        float epk = __expf(-16.f * ds * ds);
        const float WW = 0.09913725f;               // exp(-2*1.155625)
        float e = epk;
        float w = __expf(8.6f * t - 1.155625f * (2.f * istar + 1.f));
        for (int r = istar; r <= rhi; r++) {
            atomicAdd(&aev_r[sp * 16 + r], scale * e);
            e *= w; w *= WW;
        }
        e = epk;
        w = __expf(-8.6f * t + 1.155625f * (2.f * istar - 1.f));
        for (int r = istar - 1; r >= rlo; r--) {
            e *= w; w *= WW;
            atomicAdd(&aev_r[sp * 16 + r], scale * e);
        }
    }
    __syncthreads();

    // ---- pass 0: find active pairs (fc12 > 0), count per bucket ----
    for (int p = tid; p < NP; p += 128) {
        int j = (int)((47.0f - sqrtf((float)(2209 - 8 * p))) * 0.5f);
        j = max(0, min(22, j));
        while (j < 22 && BROW(j + 1) <= p) j++;
        while (j > 0 && BROW(j) > p) j--;
        int k = p - BROW(j) + j + 1;

        if (sfca_[j] > 0.f && sfca_[k] > 0.f) {
            int pi = c_triu[sspec[j] * 4 + sspec[k]];
            atomicAdd(&bcnt[pi], 1);
            int pos = atomicAdd(&nact, 1);
            plist[pos] = j | (k << 5) | (pi << 10);
        }
    }
    __syncthreads();

    if (tid == 0) {
        int o = 0;
        #pragma unroll
        for (int u = 0; u < NPAIR; u++) { boff[u] = o; o += bcnt[u]; bcnt[u] = boff[u]; }
        boff[NPAIR] = o;
    }
    __syncthreads();

    // ---- pass 1: per-active-pair math + scatter into buckets ----
    const int na = nact;
    for (int i = tid; i < na; i += 128) {
        int e  = plist[i];
        int j  = e & 31, k = (e >> 5) & 31, pi = e >> 10;
        float4 Aj = nbA[j], Ak = nbA[k];
        float4 Bj = nbB[j], Bk = nbB[k];
        float dot = Aj.x * Ak.x + Aj.y * Ak.y + Aj.z * Ak.z;
        float q   = 0.95f * dot;
        float sn  = fsqrt_a(fmaf(-q, q, 1.f));
        float fc12 = 2.f * Bj.y * Bk.y;
        float X   = __expf(-16.f * Aj.w * Ak.w);
        float f0  = Bj.w * Bk.w * X * fc12;     // fc12 folded into the g's
        float Rp  = Bj.x * Bk.x;
        float f1  = f0 * Rp * 0.0340475f;       // * exp(-3.38)
        float f2  = f1 * Rp * 3.94688e-5f;      // * exp(-10.14)
        float f3  = f2 * Rp * 4.57533e-8f;      // * exp(-16.9)
        int pos = atomicAdd(&bcnt[pi], 1);
        sq[pos]  = q;  ssn[pos] = sn;
        sg0[pos] = f0; sg1[pos] = f1; sg2[pos] = f2; sg3[pos] = f3;
    }
    __syncthreads();

    // ---- stage 2: pair-major, 10 buckets x 8 slices ----
    if (tid < NPAIR * NSL) {
        const int u  = tid >> 3;
        const int sl = tid & 7;
        float lcz[8], lsz[8];
        #pragma unroll
        for (int z = 0; z < 8; z++) { lcz[z] = c_cz[z]; lsz[z] = c_sz[z]; }

        float acc[32];
        #pragma unroll
        for (int f = 0; f < 32; f++) acc[f] = 0.f;

        const int e0 = boff[u], e1 = boff[u + 1];
        for (int idx = e0 + sl; idx < e1; idx += NSL) {
            float q  = sq[idx], sn = ssn[idx];
            float g0 = sg0[idx], g1 = sg1[idx], g2 = sg2[idx], g3 = sg3[idx];
            #pragma unroll
            for (int z = 0; z < 8; z++) {
                float cd  = fmaf(q, lcz[z], sn * lsz[z]);
                float b   = fmaf(cd, 0.5f, 0.5f);
                float b2 = b*b, b4 = b2*b2, b8 = b4*b4, b16 = b8*b8, b32 = b16*b16;
                acc[z*4+0] = fmaf(b32, g0, acc[z*4+0]);
                acc[z*4+1] = fmaf(b32, g1, acc[z*4+1]);
                acc[z*4+2] = fmaf(b32, g2, acc[z*4+2]);
                acc[z*4+3] = fmaf(b32, g3, acc[z*4+3]);
            }
        }
        #pragma unroll
        for (int f = 0; f < 32; f += 4)
            *reinterpret_cast<float4*>(&ascr[u][sl][f]) =
                make_float4(acc[f], acc[f+1], acc[f+2], acc[f+3]);
    }
    __syncthreads();

    // ---- write AEV row to global (sorted position) ----
    const int row = srow;
    if (tid < RAD) g_x0[row * AEVDIM + tid] = aev_r[tid];
    for (int t = tid; t < NPAIR * 32; t += 128) {
        int u = t >> 5, f = t & 31;
        float s = 0.f;
        #pragma unroll
        for (int sl = 0; sl < NSL; sl++) s += ascr[u][sl][f];
        g_x0[row * AEVDIM + RAD + t] = s;
    }
}

// ---------------------------------------------------------------------------
// Fused MLP: one CTA = 64 sorted rows of one species, all layers in smem.
// 512 threads, 4 rows per thread (16 warps -> 4 warps/SMSP for latency hiding)
// ---------------------------------------------------------------------------
#define A_SH_F (64 * 36)
#define W_SH_F (160 * 36)
#define H1_F   (64 * 164)
#define H2_F   (64 * 132)
#define DYN_F  (A_SH_F + W_SH_F + H1_F + H2_F)
#define MLP_T  512

extern __shared__ float dynsm[];

template<int FIN, int FOUT, int ISTR, int OSTR, bool FROMG>
__device__ __forceinline__ void layerf(
    const float* __restrict__ wT,    // [FOUT][FIN] for this species
    const float* __restrict__ bias,  // [FOUT]
    const float* __restrict__ gin,   // global rows base (FROMG)
    const float* __restrict__ in,    // smem input rows (!FROMG)
    float* __restrict__ out,         // smem output rows
    float* a_sh, float* w_sh, int m)
{
    const int tid = threadIdx.x, tx = tid & 31, ty = tid >> 5;  // ty 0..15
    constexpr int NO = FOUT / 32;

    float acc[4][NO];
    #pragma unroll
    for (int i = 0; i < 4; i++)
        #pragma unroll
        for (int jo = 0; jo < NO; jo++) acc[i][jo] = 0.f;

    for (int f0 = 0; f0 < FIN; f0 += 32) {
        __syncthreads();
        if (FROMG) {
            #pragma unroll
            for (int i = tid; i < 64 * 8; i += MLP_T) {
                int r = i >> 3, k4 = i & 7;
                int rg = min(r, m - 1);
                float4 v = *reinterpret_cast<const float4*>(&gin[rg * FIN + f0 + k4 * 4]);
                *reinterpret_cast<float4*>(&a_sh[r * 36 + k4 * 4]) = v;
            }
        }
        #pragma unroll
        for (int i = tid; i < FOUT * 8; i += MLP_T) {
            int col = i >> 3, k4 = i & 7;
            float4 v = *reinterpret_cast<const float4*>(&wT[col * FIN + f0 + k4 * 4]);
            *reinterpret_cast<float4*>(&w_sh[col * 36 + k4 * 4]) = v;
        }
        __syncthreads();

        #pragma unroll
        for (int g = 0; g < 8; g++) {
            float4 wv[NO];
            #pragma unroll
            for (int jo = 0; jo < NO; jo++)
                wv[jo] = *reinterpret_cast<const float4*>(&w_sh[(tx + 32 * jo) * 36 + 4 * g]);
            #pragma unroll
            for (int i = 0; i < 4; i++) {
                float4 av;
                if (FROMG)
                    av = *reinterpret_cast<const float4*>(&a_sh[(ty * 4 + i) * 36 + 4 * g]);
                else
                    av = *reinterpret_cast<const float4*>(&in[(ty * 4 + i) * ISTR + f0 + 4 * g]);
                #pragma unroll
                for (int jo = 0; jo < NO; jo++) {
                    acc[i][jo] = fmaf(av.x, wv[jo].x, acc[i][jo]);
                    acc[i][jo] = fmaf(av.y, wv[jo].y, acc[i][jo]);
                    acc[i][jo] = fmaf(av.z, wv[jo].z, acc[i][jo]);
                    acc[i][jo] = fmaf(av.w, wv[jo].w, acc[i][jo]);
                }
            }
        }
    }

    // epilogue: bias + CELU(0.1)
    #pragma unroll
    for (int i = 0; i < 4; i++) {
        int r = ty * 4 + i;
        if (r < m) {
            #pragma unroll
            for (int jo = 0; jo < NO; jo++) {
                int o = tx + 32 * jo;
                float v = acc[i][jo] + bias[o];
                v = (v > 0.f) ? v : 0.1f * (__expf(v * 10.f) - 1.f);
                out[r * OSTR + o] = v;
            }
        }
    }
}

__global__ __launch_bounds__(MLP_T, 1) void fused_mlp(
    const float* __restrict__ b1, const float* __restrict__ b2,
    const float* __restrict__ b3,
    const float* __restrict__ W4, const float* __restrict__ b4)
{
    const int s  = blockIdx.y;
    const int cnt = g_cnt[s];
    const int rb = blockIdx.x * 64;
    if (rb >= cnt) return;
    const int m   = min(64, cnt - rb);
    const int off = g_off[s];

    float* a_sh = dynsm;
    float* w_sh = dynsm + A_SH_F;
    float* h1   = w_sh + W_SH_F;       // stride 164 (reused as h3, stride 100)
    float* h2   = h1 + H1_F;           // stride 132

    const float* gin = g_x0 + (size_t)(off + rb) * AEVDIM;

    layerf<384, 160, 384, 164, true >(g_w1T + s * 160 * 384, b1 + s * 160, gin, h1, h1, a_sh, w_sh, m);
    layerf<160, 128, 164, 132, false>(g_w2T + s * 128 * 160, b2 + s * 128, gin, h1, h2, a_sh, w_sh, m);
    layerf<128,  96, 132, 100, false>(g_w3T + s *  96 * 128, b3 + s *  96, gin, h2, h1, a_sh, w_sh, m);
    __syncthreads();

    // layer 4: 96 -> 1 per row, write per-row energy
    const int tid = threadIdx.x;
    if (tid < m) {
        const float* w4 = W4 + s * 96;
        float a = 0.f;
        #pragma unroll
        for (int f = 0; f < 96; f += 4) {
            float4 hv = *reinterpret_cast<const float4*>(&h1[tid * 100 + f]);
            float4 wv = *reinterpret_cast<const float4*>(&w4[f]);
            a = fmaf(hv.x, wv.x, a);
            a = fmaf(hv.y, wv.y, a);
            a = fmaf(hv.z, wv.z, a);
            a = fmaf(hv.w, wv.w, a);
        }
        g_e[off + rb + tid] = a + b4[s];
    }
}

// ---------------------------------------------------------------------------
// Final: per-molecule sum of atomic energies
// ---------------------------------------------------------------------------
__global__ __launch_bounds__(64) void final_kernel(float* __restrict__ out)
{
    const int c = blockIdx.x, a = threadIdx.x;
    __shared__ float e[AA];
    e[a] = g_e[g_sortpos[c * AA + a]];
    __syncthreads();
    if (a < 32) {
        float v = e[a] + e[a + 32];
        #pragma unroll
        for (int o = 16; o; o >>= 1) v += __shfl_down_sync(0xffffffffu, v, o);
        if (a == 0) out[c] = v;
    }
}

// ---------------------------------------------------------------------------
extern "C" void kernel_launch(void* const* d_in, const int* in_sizes, int n_in,
                              void* d_out, int out_size)
{
    const int*   elem = (const int*)d_in[0];
    const int*   nbr  = (const int*)d_in[1];
    const float* dist = (const float*)d_in[2];
    const float* diff = (const float*)d_in[3];
    const float* W1 = (const float*)d_in[4],  *b1 = (const float*)d_in[5];
    const float* W2 = (const float*)d_in[6],  *b2 = (const float*)d_in[7];
    const float* W3 = (const float*)d_in[8],  *b3 = (const float*)d_in[9];
    const float* W4 = (const float*)d_in[10], *b4 = (const float*)d_in[11];
    float* out = (float*)d_out;

    const int dyn = DYN_F * (int)sizeof(float);   // 108,032 B
    cudaFuncSetAttribute(fused_mlp, cudaFuncAttributeMaxDynamicSharedMemorySize, dyn);

    sort_kernel<<<1, 256>>>(elem);
    wT_kernel<<<296, 256>>>(W1, W2, W3);
    aev_kernel<<<NATOM, 128>>>(elem, nbr, dist, diff);
    dim3 g(64, SS);
    fused_mlp<<<g, MLP_T, dyn>>>(b1, b2, b3, W4, b4);
    final_kernel<<<CC, 64>>>(out);
}